// round 1
// baseline (speedup 1.0000x reference)
#include <cuda_runtime.h>
#include <math.h>

// ---------------- problem constants ----------------
#define PB   2
#define PS   4096
#define PHID 640
#define PNH  4
#define PHD  256
#define PM   (PB * PS)        /* 8192 rows of tokens */
#define PQN  (PNH * PHD)      /* 1024 */
#define SCALE_F 0.0625f       /* 256^-0.5 */
#define CAP_F   50.0f
#define WIN_I   512
#define EPS_F   1e-6f

// ---------------- scratch (static device, no allocs) ----------------
__device__ float g_Q[(size_t)PM * PQN];   // Q projected (B,S,NH,HD)
__device__ float g_K[(size_t)PM * PHD];   // K projected (B,S,HD)
__device__ float g_V[(size_t)PM * PHD];   // V projected (B,S,HD)
__device__ float g_AO[(size_t)PM * PQN];  // attention output (B,S,NH,HD)

// =====================================================================
// SGEMM: C[M,N] = A[M,K] @ B[K,N], all row-major fp32.
// 128x128 tile, BK=8, 256 threads, 8x8 per thread (split 4+4 layout).
// Requires M%128==0, N%128==0, K%8==0 (true for all calls here).
// =====================================================================
__global__ void __launch_bounds__(256) sgemm_kernel(
    const float* __restrict__ A, const float* __restrict__ B,
    float* __restrict__ C, int M, int N, int K) {
  __shared__ float As[8][128];
  __shared__ float Bs[8][128];

  const int tid = threadIdx.x;
  const int bm = blockIdx.y * 128;
  const int bn = blockIdx.x * 128;

  const int arow = tid >> 1;          // 0..127
  const int acol = (tid & 1) * 4;     // 0 or 4
  const int brow = tid >> 5;          // 0..7
  const int bcol = (tid & 31) * 4;    // 0..124

  const int tx = tid & 15;
  const int ty = tid >> 4;

  float acc[8][8];
#pragma unroll
  for (int i = 0; i < 8; i++)
#pragma unroll
    for (int j = 0; j < 8; j++) acc[i][j] = 0.f;

  const float* Aptr = A + (size_t)(bm + arow) * K + acol;
  const float* Bptr = B + (size_t)brow * N + bn + bcol;

  for (int k0 = 0; k0 < K; k0 += 8) {
    const float4 av = *(const float4*)(Aptr + k0);
    const float4 bv = *(const float4*)(Bptr + (size_t)k0 * N);
    __syncthreads();
    As[acol + 0][arow] = av.x;
    As[acol + 1][arow] = av.y;
    As[acol + 2][arow] = av.z;
    As[acol + 3][arow] = av.w;
    *(float4*)&Bs[brow][bcol] = bv;
    __syncthreads();

#pragma unroll
    for (int kk = 0; kk < 8; kk++) {
      float a[8], b[8];
      *(float4*)(a)     = *(const float4*)&As[kk][ty * 4];
      *(float4*)(a + 4) = *(const float4*)&As[kk][64 + ty * 4];
      *(float4*)(b)     = *(const float4*)&Bs[kk][tx * 4];
      *(float4*)(b + 4) = *(const float4*)&Bs[kk][64 + tx * 4];
#pragma unroll
      for (int i = 0; i < 8; i++)
#pragma unroll
        for (int j = 0; j < 8; j++) acc[i][j] += a[i] * b[j];
    }
  }

#pragma unroll
  for (int i = 0; i < 8; i++) {
    const int r = bm + ((i < 4) ? (ty * 4 + i) : (64 + ty * 4 + i - 4));
    float* Cp = C + (size_t)r * N + bn;
    *(float4*)(Cp + tx * 4)      = make_float4(acc[i][0], acc[i][1], acc[i][2], acc[i][3]);
    *(float4*)(Cp + 64 + tx * 4) = make_float4(acc[i][4], acc[i][5], acc[i][6], acc[i][7]);
  }
}

// =====================================================================
// Fused RMSNorm (+1+w) + RoPE, in place. One block per (token, head).
// 256 threads == HD.
// =====================================================================
__global__ void __launch_bounds__(256) normrope_kernel(
    float* __restrict__ buf, const float* __restrict__ w,
    const float* __restrict__ cost, const float* __restrict__ sint, int heads) {
  const int m = blockIdx.x;   // token index in [0, B*S)
  const int h = blockIdx.y;
  const int d = threadIdx.x;

  float* p = buf + ((size_t)m * heads + h) * PHD;
  const float x = p[d];

  // block sum of squares
  float v = x * x;
#pragma unroll
  for (int o = 16; o > 0; o >>= 1) v += __shfl_xor_sync(0xffffffffu, v, o);

  __shared__ float red[8];
  __shared__ float sx[PHD];
  __shared__ float sinv;
  const int lane = d & 31, wp = d >> 5;
  if (lane == 0) red[wp] = v;
  __syncthreads();
  if (d == 0) {
    float s = 0.f;
#pragma unroll
    for (int i = 0; i < 8; i++) s += red[i];
    sinv = rsqrtf(s / (float)PHD + EPS_F);
  }
  __syncthreads();

  const float xn = x * sinv * (1.0f + w[d]);
  sx[d] = xn;
  __syncthreads();
  const float rot = (d < PHD / 2) ? -sx[d + PHD / 2] : sx[d - PHD / 2];
  const int s = m & (PS - 1);   // m % S  (S = 4096 power of two)
  p[d] = xn * cost[(size_t)s * PHD + d] + rot * sint[(size_t)s * PHD + d];
}

// =====================================================================
// Sliding-window flash attention with tanh softcap.
// Block = 256 threads handles one (b, h, 64-query tile).
// Key chunks of 64; online softmax. Mask computed analytically.
// smem: Qt[256][68] (transposed, pre-scaled), Kt[256][68] (transposed),
//       Vs[64][256], Ps[64][65], rs[64], ls[64]
// =====================================================================
#define TSTR 68
#define ATT_QT_OFF 0
#define ATT_KT_OFF (ATT_QT_OFF + 256 * TSTR)          /* 17408 */
#define ATT_VS_OFF (ATT_KT_OFF + 256 * TSTR)          /* 34816 */
#define ATT_PS_OFF (ATT_VS_OFF + 64 * 256)            /* 51200 */
#define ATT_RS_OFF (ATT_PS_OFF + 64 * 65)             /* 55360 */
#define ATT_LS_OFF (ATT_RS_OFF + 64)                  /* 55424 */
#define ATT_SMEM_FLOATS (ATT_LS_OFF + 64)             /* 55488 -> 221952 B */

__global__ void __launch_bounds__(256, 1) attn_kernel() {
  extern __shared__ float sm[];
  float* Qt = sm + ATT_QT_OFF;
  float* Kt = sm + ATT_KT_OFF;
  float* Vs = sm + ATT_VS_OFF;
  float* Ps = sm + ATT_PS_OFF;
  float* rs = sm + ATT_RS_OFF;
  float* ls = sm + ATT_LS_OFF;

  const int tid = threadIdx.x;
  const int t = blockIdx.x;      // query tile
  const int h = blockIdx.y;
  const int b = blockIdx.z;
  const int i0 = t * 64;

  const float* Qg = g_Q + ((size_t)b * PS * PNH + h) * PHD;  // + i*PQN per row
  const float* Kg = g_K + (size_t)b * PS * PHD;
  const float* Vg = g_V + (size_t)b * PS * PHD;
  float* Og = g_AO + ((size_t)b * PS * PNH + h) * PHD;

  // load Q tile transposed + pre-scaled
  for (int idx = tid; idx < 64 * 64; idx += 256) {
    const int q = idx >> 6;
    const int dv = (idx & 63) << 2;
    const float4 qv = *(const float4*)(Qg + (size_t)(i0 + q) * PQN + dv);
    Qt[(dv + 0) * TSTR + q] = qv.x * SCALE_F;
    Qt[(dv + 1) * TSTR + q] = qv.y * SCALE_F;
    Qt[(dv + 2) * TSTR + q] = qv.z * SCALE_F;
    Qt[(dv + 3) * TSTR + q] = qv.w * SCALE_F;
  }

  const int ty = tid >> 4, tx = tid & 15;
  const int qb = ty * 4, kb = tx * 4;

  float acc[4][16];
#pragma unroll
  for (int i = 0; i < 4; i++)
#pragma unroll
    for (int j = 0; j < 16; j++) acc[i][j] = 0.f;

  float mq = -1e30f, lq = 0.f;   // row state (threads tid<64 only)

  const int cstart = (t - 8 < 0) ? 0 : (t - 8);
  for (int c = cstart; c <= t; ++c) {
    const int j0 = c * 64;
    __syncthreads();   // previous PV done with Vs/Ps
    // load K (transposed) and V chunk
    for (int idx = tid; idx < 64 * 64; idx += 256) {
      const int k = idx >> 6;
      const int dv = (idx & 63) << 2;
      const float4 kv = *(const float4*)(Kg + (size_t)(j0 + k) * PHD + dv);
      Kt[(dv + 0) * TSTR + k] = kv.x;
      Kt[(dv + 1) * TSTR + k] = kv.y;
      Kt[(dv + 2) * TSTR + k] = kv.z;
      Kt[(dv + 3) * TSTR + k] = kv.w;
      *(float4*)(Vs + (size_t)k * PHD + dv) =
          *(const float4*)(Vg + (size_t)(j0 + k) * PHD + dv);
    }
    __syncthreads();

    // ---- QK: 4x4 scores per thread, outer product over d ----
    float sc[4][4];
#pragma unroll
    for (int i = 0; i < 4; i++)
#pragma unroll
      for (int j = 0; j < 4; j++) sc[i][j] = 0.f;

    const float* qp = Qt + qb;
    const float* kp = Kt + kb;
#pragma unroll 4
    for (int dv = 0; dv < PHD; ++dv) {
      const float4 qv = *(const float4*)(qp + dv * TSTR);
      const float4 kv = *(const float4*)(kp + dv * TSTR);
      sc[0][0] += qv.x * kv.x; sc[0][1] += qv.x * kv.y; sc[0][2] += qv.x * kv.z; sc[0][3] += qv.x * kv.w;
      sc[1][0] += qv.y * kv.x; sc[1][1] += qv.y * kv.y; sc[1][2] += qv.y * kv.z; sc[1][3] += qv.y * kv.w;
      sc[2][0] += qv.z * kv.x; sc[2][1] += qv.z * kv.y; sc[2][2] += qv.z * kv.z; sc[2][3] += qv.z * kv.w;
      sc[3][0] += qv.w * kv.x; sc[3][1] += qv.w * kv.y; sc[3][2] += qv.w * kv.z; sc[3][3] += qv.w * kv.w;
    }

    // softcap + analytic sliding causal mask, write to Ps
#pragma unroll
    for (int qi = 0; qi < 4; ++qi) {
      const int gi = i0 + qb + qi;
#pragma unroll
      for (int kj = 0; kj < 4; ++kj) {
        const int gj = j0 + kb + kj;
        const float capped = CAP_F * tanhf(sc[qi][kj] * (1.0f / CAP_F));
        const bool ok = (gj <= gi) && (gj > gi - WIN_I);
        Ps[(qb + qi) * 65 + (kb + kj)] = ok ? capped : -1e9f;
      }
    }
    __syncthreads();

    // ---- online softmax: one thread per row ----
    if (tid < 64) {
      float* pr = Ps + tid * 65;
      float mc = -1e30f;
#pragma unroll 8
      for (int k = 0; k < 64; ++k) mc = fmaxf(mc, pr[k]);
      const float mNew = fmaxf(mq, mc);
      const float r = __expf(mq - mNew);
      float sum = 0.f;
#pragma unroll 8
      for (int k = 0; k < 64; ++k) {
        const float sv = pr[k];
        const float p = (sv > -1e8f) ? __expf(sv - mNew) : 0.f;
        pr[k] = p;
        sum += p;
      }
      lq = lq * r + sum;
      mq = mNew;
      rs[tid] = r;
      ls[tid] = lq;
    }
    __syncthreads();

    // ---- PV: rescale + accumulate ----
#pragma unroll
    for (int qi = 0; qi < 4; ++qi) {
      const float rr = rs[qb + qi];
#pragma unroll
      for (int j = 0; j < 16; ++j) acc[qi][j] *= rr;
    }
    const float* vp = Vs + tx * 4;
#pragma unroll 2
    for (int k = 0; k < 64; ++k) {
      float vv[16];
      *(float4*)(vv)      = *(const float4*)(vp + (size_t)k * PHD);
      *(float4*)(vv + 4)  = *(const float4*)(vp + (size_t)k * PHD + 64);
      *(float4*)(vv + 8)  = *(const float4*)(vp + (size_t)k * PHD + 128);
      *(float4*)(vv + 12) = *(const float4*)(vp + (size_t)k * PHD + 192);
#pragma unroll
      for (int qi = 0; qi < 4; ++qi) {
        const float p = Ps[(qb + qi) * 65 + k];
#pragma unroll
        for (int j = 0; j < 16; ++j) acc[qi][j] += p * vv[j];
      }
    }
  }

  // epilogue: divide by l, store
#pragma unroll
  for (int qi = 0; qi < 4; ++qi) {
    const float inv = 1.0f / ls[qb + qi];
    float* op = Og + (size_t)(i0 + qb + qi) * PQN;
#pragma unroll
    for (int g = 0; g < 4; ++g) {
      float4 o;
      o.x = acc[qi][g * 4 + 0] * inv;
      o.y = acc[qi][g * 4 + 1] * inv;
      o.z = acc[qi][g * 4 + 2] * inv;
      o.w = acc[qi][g * 4 + 3] * inv;
      *(float4*)(op + g * 64 + tx * 4) = o;
    }
  }
}

// =====================================================================
// launch
// =====================================================================
extern "C" void kernel_launch(void* const* d_in, const int* in_sizes, int n_in,
                              void* d_out, int out_size) {
  (void)in_sizes; (void)n_in; (void)out_size;
  const float* hidden = (const float*)d_in[0];
  const float* cost   = (const float*)d_in[1];
  const float* sint   = (const float*)d_in[2];
  // d_in[3] attention_mask: intentionally unused (mask computed analytically)
  const float* Wq = (const float*)d_in[4];
  const float* Wk = (const float*)d_in[5];
  const float* Wv = (const float*)d_in[6];
  const float* Wo = (const float*)d_in[7];
  const float* qw = (const float*)d_in[8];
  const float* kw = (const float*)d_in[9];
  float* out = (float*)d_out;

  float *Qb, *Kb, *Vb, *AOb;
  cudaGetSymbolAddress((void**)&Qb, g_Q);
  cudaGetSymbolAddress((void**)&Kb, g_K);
  cudaGetSymbolAddress((void**)&Vb, g_V);
  cudaGetSymbolAddress((void**)&AOb, g_AO);

  const dim3 blk(256);

  // QKV projections
  sgemm_kernel<<<dim3(PQN / 128, PM / 128), blk>>>(hidden, Wq, Qb, PM, PQN, PHID);
  sgemm_kernel<<<dim3(PHD / 128, PM / 128), blk>>>(hidden, Wk, Kb, PM, PHD, PHID);
  sgemm_kernel<<<dim3(PHD / 128, PM / 128), blk>>>(hidden, Wv, Vb, PM, PHD, PHID);

  // RMSNorm + RoPE
  normrope_kernel<<<dim3(PM, PNH), 256>>>(Qb, qw, cost, sint, PNH);
  normrope_kernel<<<dim3(PM, 1), 256>>>(Kb, kw, cost, sint, 1);

  // attention
  const int smem_bytes = ATT_SMEM_FLOATS * (int)sizeof(float);
  cudaFuncSetAttribute(attn_kernel, cudaFuncAttributeMaxDynamicSharedMemorySize, smem_bytes);
  attn_kernel<<<dim3(PS / 64, PNH, PB), 256, smem_bytes>>>();

  // output projection
  sgemm_kernel<<<dim3(PHID / 128, PM / 128), blk>>>(AOb, Wo, out, PM, PHID, PQN);
}

// round 3
// speedup vs baseline: 1.2568x; 1.2568x over previous
#include <cuda_runtime.h>
#include <cuda_bf16.h>
#include <math.h>
#include <stdint.h>

// ---------------- problem constants ----------------
#define PB   2
#define PS   4096
#define PHID 640
#define PNH  4
#define PHD  256
#define PM   (PB * PS)        /* 8192 rows of tokens */
#define PQN  (PNH * PHD)      /* 1024 */
#define SCALE_F 0.0625f       /* 256^-0.5 */
#define CAP_F   50.0f
#define WIN_I   512
#define EPS_F   1e-6f

// ---------------- scratch (static device, no allocs) ----------------
__device__ float g_Q[(size_t)PM * PQN];   // Q projected (B,S,NH,HD)
__device__ float g_K[(size_t)PM * PHD];   // K projected (B,S,HD)
__device__ float g_V[(size_t)PM * PHD];   // V projected (B,S,HD)
__device__ float g_AO[(size_t)PM * PQN];  // attention output (B,S,NH,HD)

// =====================================================================
// bf16-split helpers: x = hi + lo with hi = truncate-to-bf16(x),
// lo = rn-bf16(x - hi). Product A*B ~= Ah*Bh + Ah*Bl + Al*Bh
// (dropped Al*Bl term ~2^-14 relative).
// =====================================================================
__device__ __forceinline__ void split2(float x, float y, uint32_t& hi, uint32_t& lo) {
  const uint32_t xb = __float_as_uint(x);
  const uint32_t yb = __float_as_uint(y);
  hi = (xb >> 16) | (yb & 0xffff0000u);
  const float xr = x - __uint_as_float(xb & 0xffff0000u);
  const float yr = y - __uint_as_float(yb & 0xffff0000u);
  union { __nv_bfloat162 h; uint32_t u; } cv;
  cv.h = __floats2bfloat162_rn(xr, yr);
  lo = cv.u;
}

__device__ __forceinline__ void mma_bf16(float* d, const uint32_t* a, const uint32_t* b) {
  asm volatile(
      "mma.sync.aligned.m16n8k16.row.col.f32.bf16.bf16.f32 "
      "{%0,%1,%2,%3}, {%4,%5,%6,%7}, {%8,%9}, {%0,%1,%2,%3};\n"
      : "+f"(d[0]), "+f"(d[1]), "+f"(d[2]), "+f"(d[3])
      : "r"(a[0]), "r"(a[1]), "r"(a[2]), "r"(a[3]), "r"(b[0]), "r"(b[1]));
}

// =====================================================================
// Tensor-core GEMM: C[M,N] = A[M,K] @ B[K,N], fp32 in/out,
// bf16x3 compensated mma. 128x128x32 tiles, 256 threads (8 warps 2x4),
// each warp 64x32 = 4x4 m16n8k16 tiles. Requires M%128==0, N%128==0,
// K%32==0 (true for all calls).
// =====================================================================
__global__ void __launch_bounds__(256) gemm_tc(
    const float* __restrict__ A, const float* __restrict__ B,
    float* __restrict__ C, int M, int N, int K) {
  __shared__ float As[128][36];   // [m][k], pad 36
  __shared__ float Bs[128][32];   // [n][k], swizzled: k ^ (((n>>2)&7)<<2)

  const int tid = threadIdx.x;
  const int bm = blockIdx.y * 128;
  const int bn = blockIdx.x * 128;
  const int wid = tid >> 5;
  const int lane = tid & 31;
  const int g  = lane >> 2;          // 0..7
  const int tg = lane & 3;           // 0..3
  const int warp_m = (wid >> 2) * 64;   // 0 or 64
  const int warp_n = (wid & 3) * 32;    // 0,32,64,96

  float acc[4][4][4];
#pragma unroll
  for (int i = 0; i < 4; i++)
#pragma unroll
    for (int j = 0; j < 4; j++)
#pragma unroll
      for (int l = 0; l < 4; l++) acc[i][j][l] = 0.f;

  // global staging indices
  const int ar  = tid >> 3;          // 0..31 (A row group)
  const int ac  = (tid & 7) * 4;     // 0..28 (A col)
  const int bk  = tid >> 5;          // 0..7  (B k row)
  const int bn4 = (tid & 31) * 4;    // 0..124 (B n col)

  float4 ga[4], gb[4];
#pragma unroll
  for (int i = 0; i < 4; i++)
    ga[i] = *(const float4*)(A + (size_t)(bm + ar + i * 32) * K + ac);
#pragma unroll
  for (int i = 0; i < 4; i++)
    gb[i] = *(const float4*)(B + (size_t)(bk + i * 8) * N + bn + bn4);

  for (int k0 = 0; k0 < K; k0 += 32) {
    __syncthreads();   // previous compute done with smem
#pragma unroll
    for (int i = 0; i < 4; i++)
      *(float4*)&As[ar + i * 32][ac] = ga[i];
#pragma unroll
    for (int i = 0; i < 4; i++) {
      const int kk = bk + i * 8;
      const float4 v = gb[i];
      Bs[bn4 + 0][kk ^ ((((bn4 + 0) >> 2) & 7) << 2)] = v.x;
      Bs[bn4 + 1][kk ^ ((((bn4 + 1) >> 2) & 7) << 2)] = v.y;
      Bs[bn4 + 2][kk ^ ((((bn4 + 2) >> 2) & 7) << 2)] = v.z;
      Bs[bn4 + 3][kk ^ ((((bn4 + 3) >> 2) & 7) << 2)] = v.w;
    }
    __syncthreads();

    // prefetch next tile into registers (hidden under compute)
    if (k0 + 32 < K) {
#pragma unroll
      for (int i = 0; i < 4; i++)
        ga[i] = *(const float4*)(A + (size_t)(bm + ar + i * 32) * K + (k0 + 32 + ac));
#pragma unroll
      for (int i = 0; i < 4; i++)
        gb[i] = *(const float4*)(B + (size_t)(k0 + 32 + bk + i * 8) * N + bn + bn4);
    }

#pragma unroll
    for (int ks = 0; ks < 32; ks += 16) {
      // B fragments (hi/lo) for 4 n-tiles
      uint32_t bh[4][2], bl[4][2];
#pragma unroll
      for (int nt = 0; nt < 4; nt++) {
        const int n = warp_n + nt * 8 + g;
        const int c = ((n >> 2) & 7) << 2;
        const float2 q0 = *(const float2*)&Bs[n][(ks + 2 * tg) ^ c];
        const float2 q1 = *(const float2*)&Bs[n][(ks + 2 * tg + 8) ^ c];
        split2(q0.x, q0.y, bh[nt][0], bl[nt][0]);
        split2(q1.x, q1.y, bh[nt][1], bl[nt][1]);
      }
#pragma unroll
      for (int mt = 0; mt < 4; mt++) {
        const int m = warp_m + mt * 16;
        const float2 p0 = *(const float2*)&As[m + g][ks + 2 * tg];
        const float2 p1 = *(const float2*)&As[m + g + 8][ks + 2 * tg];
        const float2 p2 = *(const float2*)&As[m + g][ks + 2 * tg + 8];
        const float2 p3 = *(const float2*)&As[m + g + 8][ks + 2 * tg + 8];
        uint32_t ah[4], al[4];
        split2(p0.x, p0.y, ah[0], al[0]);
        split2(p1.x, p1.y, ah[1], al[1]);
        split2(p2.x, p2.y, ah[2], al[2]);
        split2(p3.x, p3.y, ah[3], al[3]);
#pragma unroll
        for (int nt = 0; nt < 4; nt++) {
          mma_bf16(acc[mt][nt], ah, bh[nt]);
          mma_bf16(acc[mt][nt], ah, bl[nt]);
          mma_bf16(acc[mt][nt], al, bh[nt]);
        }
      }
    }
  }

  // epilogue
#pragma unroll
  for (int mt = 0; mt < 4; mt++) {
    const int r0 = bm + warp_m + mt * 16 + g;
#pragma unroll
    for (int nt = 0; nt < 4; nt++) {
      const int cc = bn + warp_n + nt * 8 + 2 * tg;
      *(float2*)(C + (size_t)r0 * N + cc)       = make_float2(acc[mt][nt][0], acc[mt][nt][1]);
      *(float2*)(C + (size_t)(r0 + 8) * N + cc) = make_float2(acc[mt][nt][2], acc[mt][nt][3]);
    }
  }
}

// =====================================================================
// Fused RMSNorm (+1+w) + RoPE, in place. One block per (token, head).
// =====================================================================
__global__ void __launch_bounds__(256) normrope_kernel(
    float* __restrict__ buf, const float* __restrict__ w,
    const float* __restrict__ cost, const float* __restrict__ sint, int heads) {
  const int m = blockIdx.x;
  const int h = blockIdx.y;
  const int d = threadIdx.x;

  float* p = buf + ((size_t)m * heads + h) * PHD;
  const float x = p[d];

  float v = x * x;
#pragma unroll
  for (int o = 16; o > 0; o >>= 1) v += __shfl_xor_sync(0xffffffffu, v, o);

  __shared__ float red[8];
  __shared__ float sx[PHD];
  __shared__ float sinv;
  const int lane = d & 31, wp = d >> 5;
  if (lane == 0) red[wp] = v;
  __syncthreads();
  if (d == 0) {
    float s = 0.f;
#pragma unroll
    for (int i = 0; i < 8; i++) s += red[i];
    sinv = rsqrtf(s / (float)PHD + EPS_F);
  }
  __syncthreads();

  const float xn = x * sinv * (1.0f + w[d]);
  sx[d] = xn;
  __syncthreads();
  const float rot = (d < PHD / 2) ? -sx[d + PHD / 2] : sx[d - PHD / 2];
  const int s = m & (PS - 1);
  p[d] = xn * cost[(size_t)s * PHD + d] + rot * sint[(size_t)s * PHD + d];
}

// =====================================================================
// Sliding-window flash attention with tanh softcap (fp32).
// =====================================================================
#define TSTR 68
#define ATT_QT_OFF 0
#define ATT_KT_OFF (ATT_QT_OFF + 256 * TSTR)
#define ATT_VS_OFF (ATT_KT_OFF + 256 * TSTR)
#define ATT_PS_OFF (ATT_VS_OFF + 64 * 256)
#define ATT_RS_OFF (ATT_PS_OFF + 64 * 65)
#define ATT_LS_OFF (ATT_RS_OFF + 64)
#define ATT_SMEM_FLOATS (ATT_LS_OFF + 64)

__global__ void __launch_bounds__(256, 1) attn_kernel() {
  extern __shared__ float sm[];
  float* Qt = sm + ATT_QT_OFF;
  float* Kt = sm + ATT_KT_OFF;
  float* Vs = sm + ATT_VS_OFF;
  float* Ps = sm + ATT_PS_OFF;
  float* rs = sm + ATT_RS_OFF;
  float* ls = sm + ATT_LS_OFF;

  const int tid = threadIdx.x;
  const int t = blockIdx.x;
  const int h = blockIdx.y;
  const int b = blockIdx.z;
  const int i0 = t * 64;

  const float* Qg = g_Q + ((size_t)b * PS * PNH + h) * PHD;
  const float* Kg = g_K + (size_t)b * PS * PHD;
  const float* Vg = g_V + (size_t)b * PS * PHD;
  float* Og = g_AO + ((size_t)b * PS * PNH + h) * PHD;

  for (int idx = tid; idx < 64 * 64; idx += 256) {
    const int q = idx >> 6;
    const int dv = (idx & 63) << 2;
    const float4 qv = *(const float4*)(Qg + (size_t)(i0 + q) * PQN + dv);
    Qt[(dv + 0) * TSTR + q] = qv.x * SCALE_F;
    Qt[(dv + 1) * TSTR + q] = qv.y * SCALE_F;
    Qt[(dv + 2) * TSTR + q] = qv.z * SCALE_F;
    Qt[(dv + 3) * TSTR + q] = qv.w * SCALE_F;
  }

  const int ty = tid >> 4, tx = tid & 15;
  const int qb = ty * 4, kb = tx * 4;

  float acc[4][16];
#pragma unroll
  for (int i = 0; i < 4; i++)
#pragma unroll
    for (int j = 0; j < 16; j++) acc[i][j] = 0.f;

  float mq = -1e30f, lq = 0.f;

  const int cstart = (t - 8 < 0) ? 0 : (t - 8);
  for (int c = cstart; c <= t; ++c) {
    const int j0 = c * 64;
    __syncthreads();
    for (int idx = tid; idx < 64 * 64; idx += 256) {
      const int k = idx >> 6;
      const int dv = (idx & 63) << 2;
      const float4 kv = *(const float4*)(Kg + (size_t)(j0 + k) * PHD + dv);
      Kt[(dv + 0) * TSTR + k] = kv.x;
      Kt[(dv + 1) * TSTR + k] = kv.y;
      Kt[(dv + 2) * TSTR + k] = kv.z;
      Kt[(dv + 3) * TSTR + k] = kv.w;
      *(float4*)(Vs + (size_t)k * PHD + dv) =
          *(const float4*)(Vg + (size_t)(j0 + k) * PHD + dv);
    }
    __syncthreads();

    float sc[4][4];
#pragma unroll
    for (int i = 0; i < 4; i++)
#pragma unroll
      for (int j = 0; j < 4; j++) sc[i][j] = 0.f;

    const float* qp = Qt + qb;
    const float* kp = Kt + kb;
#pragma unroll 4
    for (int dv = 0; dv < PHD; ++dv) {
      const float4 qv = *(const float4*)(qp + dv * TSTR);
      const float4 kv = *(const float4*)(kp + dv * TSTR);
      sc[0][0] += qv.x * kv.x; sc[0][1] += qv.x * kv.y; sc[0][2] += qv.x * kv.z; sc[0][3] += qv.x * kv.w;
      sc[1][0] += qv.y * kv.x; sc[1][1] += qv.y * kv.y; sc[1][2] += qv.y * kv.z; sc[1][3] += qv.y * kv.w;
      sc[2][0] += qv.z * kv.x; sc[2][1] += qv.z * kv.y; sc[2][2] += qv.z * kv.z; sc[2][3] += qv.z * kv.w;
      sc[3][0] += qv.w * kv.x; sc[3][1] += qv.w * kv.y; sc[3][2] += qv.w * kv.z; sc[3][3] += qv.w * kv.w;
    }

#pragma unroll
    for (int qi = 0; qi < 4; ++qi) {
      const int gi = i0 + qb + qi;
#pragma unroll
      for (int kj = 0; kj < 4; ++kj) {
        const int gj = j0 + kb + kj;
        const float capped = CAP_F * tanhf(sc[qi][kj] * (1.0f / CAP_F));
        const bool ok = (gj <= gi) && (gj > gi - WIN_I);
        Ps[(qb + qi) * 65 + (kb + kj)] = ok ? capped : -1e9f;
      }
    }
    __syncthreads();

    if (tid < 64) {
      float* pr = Ps + tid * 65;
      float mc = -1e30f;
#pragma unroll 8
      for (int k = 0; k < 64; ++k) mc = fmaxf(mc, pr[k]);
      const float mNew = fmaxf(mq, mc);
      const float r = __expf(mq - mNew);
      float sum = 0.f;
#pragma unroll 8
      for (int k = 0; k < 64; ++k) {
        const float sv = pr[k];
        const float p = (sv > -1e8f) ? __expf(sv - mNew) : 0.f;
        pr[k] = p;
        sum += p;
      }
      lq = lq * r + sum;
      mq = mNew;
      rs[tid] = r;
      ls[tid] = lq;
    }
    __syncthreads();

#pragma unroll
    for (int qi = 0; qi < 4; ++qi) {
      const float rr = rs[qb + qi];
#pragma unroll
      for (int j = 0; j < 16; ++j) acc[qi][j] *= rr;
    }
    const float* vp = Vs + tx * 4;
#pragma unroll 2
    for (int k = 0; k < 64; ++k) {
      float vv[16];
      *(float4*)(vv)      = *(const float4*)(vp + (size_t)k * PHD);
      *(float4*)(vv + 4)  = *(const float4*)(vp + (size_t)k * PHD + 64);
      *(float4*)(vv + 8)  = *(const float4*)(vp + (size_t)k * PHD + 128);
      *(float4*)(vv + 12) = *(const float4*)(vp + (size_t)k * PHD + 192);
#pragma unroll
      for (int qi = 0; qi < 4; ++qi) {
        const float p = Ps[(qb + qi) * 65 + k];
#pragma unroll
        for (int j = 0; j < 16; ++j) acc[qi][j] += p * vv[j];
      }
    }
  }

#pragma unroll
  for (int qi = 0; qi < 4; ++qi) {
    const float inv = 1.0f / ls[qb + qi];
    float* op = Og + (size_t)(i0 + qb + qi) * PQN;
#pragma unroll
    for (int g = 0; g < 4; ++g) {
      float4 o;
      o.x = acc[qi][g * 4 + 0] * inv;
      o.y = acc[qi][g * 4 + 1] * inv;
      o.z = acc[qi][g * 4 + 2] * inv;
      o.w = acc[qi][g * 4 + 3] * inv;
      *(float4*)(op + g * 64 + tx * 4) = o;
    }
  }
}

// =====================================================================
// launch
// =====================================================================
extern "C" void kernel_launch(void* const* d_in, const int* in_sizes, int n_in,
                              void* d_out, int out_size) {
  (void)in_sizes; (void)n_in; (void)out_size;
  const float* hidden = (const float*)d_in[0];
  const float* cost   = (const float*)d_in[1];
  const float* sint   = (const float*)d_in[2];
  // d_in[3] attention_mask: unused (mask computed analytically)
  const float* Wq = (const float*)d_in[4];
  const float* Wk = (const float*)d_in[5];
  const float* Wv = (const float*)d_in[6];
  const float* Wo = (const float*)d_in[7];
  const float* qw = (const float*)d_in[8];
  const float* kw = (const float*)d_in[9];
  float* out = (float*)d_out;

  float *Qb, *Kb, *Vb, *AOb;
  cudaGetSymbolAddress((void**)&Qb, g_Q);
  cudaGetSymbolAddress((void**)&Kb, g_K);
  cudaGetSymbolAddress((void**)&Vb, g_V);
  cudaGetSymbolAddress((void**)&AOb, g_AO);

  const dim3 blk(256);

  // QKV projections (tensor-core bf16x3)
  gemm_tc<<<dim3(PQN / 128, PM / 128), blk>>>(hidden, Wq, Qb, PM, PQN, PHID);
  gemm_tc<<<dim3(PHD / 128, PM / 128), blk>>>(hidden, Wk, Kb, PM, PHD, PHID);
  gemm_tc<<<dim3(PHD / 128, PM / 128), blk>>>(hidden, Wv, Vb, PM, PHD, PHID);

  // RMSNorm + RoPE
  normrope_kernel<<<dim3(PM, PNH), 256>>>(Qb, qw, cost, sint, PNH);
  normrope_kernel<<<dim3(PM, 1), 256>>>(Kb, kw, cost, sint, 1);

  // attention
  const int smem_bytes = ATT_SMEM_FLOATS * (int)sizeof(float);
  cudaFuncSetAttribute(attn_kernel, cudaFuncAttributeMaxDynamicSharedMemorySize, smem_bytes);
  attn_kernel<<<dim3(PS / 64, PNH, PB), 256, smem_bytes>>>();

  // output projection
  gemm_tc<<<dim3(PHID / 128, PM / 128), blk>>>(AOb, Wo, out, PM, PHID, PQN);
}

// round 11
// speedup vs baseline: 1.4496x; 1.1534x over previous
#include <cuda_runtime.h>
#include <cuda_bf16.h>
#include <math.h>
#include <stdint.h>

// ---------------- problem constants ----------------
#define PB   2
#define PS   4096
#define PHID 640
#define PNH  4
#define PHD  256
#define PM   (PB * PS)        /* 8192 token rows */
#define PQN  (PNH * PHD)      /* 1024 */
#define LDQKV 1536            /* combined QKV row: 1024 Q + 256 K + 256 V */
#define SCALE_F 0.0625f
#define CAP_F   50.0f
#define WIN_I   512
#define EPS_F   1e-6f

// ---------------- scratch (static device, no allocs) ----------------
__device__ float g_QKV[(size_t)PM * LDQKV];  // fused QKV output fp32
__device__ float g_AO[(size_t)PM * PQN];     // attention output fp32

__device__ unsigned short g_Ah[(size_t)PM * PHID];      // hidden hi [M][640]
__device__ unsigned short g_Al[(size_t)PM * PHID];
__device__ unsigned short g_WBh[(size_t)LDQKV * PHID];  // [Wq^T;Wk^T;Wv^T] hi [1536][640]
__device__ unsigned short g_WBl[(size_t)LDQKV * PHID];
__device__ unsigned short g_Woh[(size_t)PHID * PQN];    // Wo^T hi [640][1024]
__device__ unsigned short g_Wol[(size_t)PHID * PQN];
__device__ unsigned short g_AOh[(size_t)PM * PQN];
__device__ unsigned short g_AOl[(size_t)PM * PQN];

// =====================================================================
// split helpers: x = hi + lo, hi = truncate-to-bf16, lo = rn-bf16(x-hi)
// =====================================================================
__device__ __forceinline__ void split1(float x, unsigned short& h, unsigned short& l) {
  const uint32_t xb = __float_as_uint(x);
  h = (unsigned short)(xb >> 16);
  const float r = x - __uint_as_float(xb & 0xffff0000u);
  __nv_bfloat16 lb = __float2bfloat16(r);
  l = *reinterpret_cast<unsigned short*>(&lb);
}

__global__ void __launch_bounds__(256) split_elem(
    const float4* __restrict__ src, ushort4* __restrict__ hi,
    ushort4* __restrict__ lo, int n4) {
  const int i = blockIdx.x * 256 + threadIdx.x;
  if (i >= n4) return;
  const float4 v = src[i];
  ushort4 h, l;
  split1(v.x, h.x, l.x);
  split1(v.y, h.y, l.y);
  split1(v.z, h.z, l.z);
  split1(v.w, h.w, l.w);
  hi[i] = h;
  lo[i] = l;
}

// transpose + split: W[K][N] -> Th/Tl [N][K].  K,N divisible by 32.
__global__ void __launch_bounds__(256) transpose_split(
    const float* __restrict__ W, unsigned short* __restrict__ Th,
    unsigned short* __restrict__ Tl, int Kd, int Nd) {
  __shared__ float ts[32][33];
  const int kt = blockIdx.x * 32;
  const int nt = blockIdx.y * 32;
  const int tx = threadIdx.x & 31;
  const int ty = threadIdx.x >> 5;
#pragma unroll
  for (int i = 0; i < 4; i++)
    ts[ty + i * 8][tx] = W[(size_t)(kt + ty + i * 8) * Nd + nt + tx];
  __syncthreads();
#pragma unroll
  for (int i = 0; i < 4; i++) {
    const int r = ty + i * 8;
    const float v = ts[tx][r];
    unsigned short h, l;
    split1(v, h, l);
    Th[(size_t)(nt + r) * Kd + kt + tx] = h;
    Tl[(size_t)(nt + r) * Kd + kt + tx] = l;
  }
}

// =====================================================================
// mma / ldmatrix primitives
// =====================================================================
__device__ __forceinline__ void mma16816(float* d, const uint32_t* a, const uint32_t* b) {
  asm volatile(
      "mma.sync.aligned.m16n8k16.row.col.f32.bf16.bf16.f32 "
      "{%0,%1,%2,%3}, {%4,%5,%6,%7}, {%8,%9}, {%0,%1,%2,%3};\n"
      : "+f"(d[0]), "+f"(d[1]), "+f"(d[2]), "+f"(d[3])
      : "r"(a[0]), "r"(a[1]), "r"(a[2]), "r"(a[3]), "r"(b[0]), "r"(b[1]));
}

__device__ __forceinline__ void ldmx4(uint32_t* r, uint32_t addr) {
  asm volatile("ldmatrix.sync.aligned.m8n8.x4.shared.b16 {%0,%1,%2,%3}, [%4];"
               : "=r"(r[0]), "=r"(r[1]), "=r"(r[2]), "=r"(r[3]) : "r"(addr));
}
__device__ __forceinline__ void ldmx2(uint32_t* r, uint32_t addr) {
  asm volatile("ldmatrix.sync.aligned.m8n8.x2.shared.b16 {%0,%1}, [%2];"
               : "=r"(r[0]), "=r"(r[1]) : "r"(addr));
}

// =====================================================================
// Tensor-core GEMM, pre-split bf16 operands:
//   C[M,N] = Ah.Bh^T + Ah.Bl^T + Al.Bh^T   (fp32 out)
// A* [M][K] bf16 K-major; B* [N][K] bf16 K-major. 128x128x32 tiles,
// 256 threads (8 warps 2x4, warp = 64x32). cp.async double buffered.
// Smem tile layout: pair-rows of 128B with XOR swizzle
//   unit(m,kc) = (m>>1)*8 + (((m&1)*4+kc) ^ ((m>>1)&7)),  kc = k16B-unit 0..3
// -> conflict-free cp.async stores and ldmatrix reads.
// M,N div 128; K div 32.
// =====================================================================
#define GT_TILE  8192u                 /* 128 x 32 bf16 = 8KB */
#define GT_STAGE (4u * GT_TILE)        /* Ah, Al, Bh, Bl */
#define GT_SMEM  (2u * GT_STAGE)       /* 64KB */

__device__ __forceinline__ void gt_issue(
    const unsigned short* __restrict__ Ah, const unsigned short* __restrict__ Al,
    const unsigned short* __restrict__ Bh, const unsigned short* __restrict__ Bl,
    int bm, int bn, int K, int c, uint32_t stage_base, int tid) {
  const unsigned short* srcs[4] = {Ah, Al, Bh, Bl};
#pragma unroll
  for (int t = 0; t < 4; ++t) {
    const unsigned short* src = srcs[t];
    const int r0 = (t < 2) ? bm : bn;
    const uint32_t tb = stage_base + (uint32_t)t * GT_TILE;
#pragma unroll
    for (int j = 0; j < 2; ++j) {
      const int u = tid + j * 256;       // 0..511 16B-units
      const int p = u >> 3;
      const int w = u & 7;
      const int m = p * 2 + (w >> 2);
      const int kc = w & 3;
      const unsigned short* g = src + (size_t)(r0 + m) * K + c * 32 + kc * 8;
      const uint32_t sa = tb + (uint32_t)((p * 8 + (w ^ (p & 7))) * 16);
      asm volatile("cp.async.cg.shared.global [%0], [%1], 16;" :: "r"(sa), "l"(g) : "memory");
    }
  }
  asm volatile("cp.async.commit_group;" ::: "memory");
}

__global__ void __launch_bounds__(256) gemm_mma(
    const unsigned short* __restrict__ Ah, const unsigned short* __restrict__ Al,
    const unsigned short* __restrict__ Bh, const unsigned short* __restrict__ Bl,
    float* __restrict__ C, int M, int N, int K) {
  extern __shared__ char smem[];
  const uint32_t sbase = (uint32_t)__cvta_generic_to_shared(smem);

  const int tid = threadIdx.x;
  const int wid = tid >> 5;
  const int lane = tid & 31;
  const int bm = blockIdx.y * 128;
  const int bn = blockIdx.x * 128;
  const int warp_m = (wid >> 2) * 64;
  const int warp_n = (wid & 3) * 32;
  const int nc = K >> 5;

  float acc[4][4][4];
#pragma unroll
  for (int i = 0; i < 4; i++)
#pragma unroll
    for (int j = 0; j < 4; j++)
#pragma unroll
      for (int l = 0; l < 4; l++) acc[i][j][l] = 0.f;

  gt_issue(Ah, Al, Bh, Bl, bm, bn, K, 0, sbase, tid);

  for (int c = 0; c < nc; ++c) {
    if (c + 1 < nc) {
      gt_issue(Ah, Al, Bh, Bl, bm, bn, K, c + 1,
               sbase + (uint32_t)((c + 1) & 1) * GT_STAGE, tid);
      asm volatile("cp.async.wait_group 1;" ::: "memory");
    } else {
      asm volatile("cp.async.wait_group 0;" ::: "memory");
    }
    __syncthreads();

    const uint32_t st = sbase + (uint32_t)(c & 1) * GT_STAGE;
    const uint32_t TAh = st;
    const uint32_t TAl = st + GT_TILE;
    const uint32_t TBh = st + 2 * GT_TILE;
    const uint32_t TBl = st + 3 * GT_TILE;

#pragma unroll
    for (int ks = 0; ks < 2; ++ks) {
      uint32_t bh[4][2], bl[4][2];
#pragma unroll
      for (int nt = 0; nt < 4; ++nt) {
        const int n = warp_n + nt * 8 + (lane & 7);
        const int kc = ks * 2 + ((lane >> 3) & 1);
        const int pn = n >> 1;
        const uint32_t off =
            (uint32_t)((pn * 8 + (((n & 1) * 4 + kc) ^ (pn & 7))) * 16);
        ldmx2(bh[nt], TBh + off);
        ldmx2(bl[nt], TBl + off);
      }
#pragma unroll
      for (int mt = 0; mt < 4; ++mt) {
        const int m = warp_m + mt * 16 + (lane & 15);
        const int kc = ks * 2 + (lane >> 4);
        const int pm = m >> 1;
        const uint32_t off =
            (uint32_t)((pm * 8 + (((m & 1) * 4 + kc) ^ (pm & 7))) * 16);
        uint32_t ah[4], al[4];
        ldmx4(ah, TAh + off);
        ldmx4(al, TAl + off);
#pragma unroll
        for (int nt = 0; nt < 4; ++nt) {
          mma16816(acc[mt][nt], ah, bh[nt]);
          mma16816(acc[mt][nt], ah, bl[nt]);
          mma16816(acc[mt][nt], al, bh[nt]);
        }
      }
    }
    __syncthreads();
  }

  // epilogue: fragment rows -> global fp32
#pragma unroll
  for (int mt = 0; mt < 4; ++mt) {
    const int r = bm + warp_m + mt * 16 + (lane >> 2);
#pragma unroll
    for (int nt = 0; nt < 4; ++nt) {
      const int cc = bn + warp_n + nt * 8 + 2 * (lane & 3);
      *(float2*)(C + (size_t)r * N + cc) = make_float2(acc[mt][nt][0], acc[mt][nt][1]);
      *(float2*)(C + (size_t)(r + 8) * N + cc) = make_float2(acc[mt][nt][2], acc[mt][nt][3]);
    }
  }
}

// =====================================================================
// Fused RMSNorm (+1+w) + RoPE, in place on strided buffer.
// grid (PM, heads); row = buf + m*ld + h*PHD.
// =====================================================================
__global__ void __launch_bounds__(256) normrope_kernel(
    float* __restrict__ buf, int ld, const float* __restrict__ w,
    const float* __restrict__ cost, const float* __restrict__ sint) {
  const int m = blockIdx.x;
  const int h = blockIdx.y;
  const int d = threadIdx.x;

  float* p = buf + (size_t)m * ld + h * PHD;
  const float x = p[d];

  float v = x * x;
#pragma unroll
  for (int o = 16; o > 0; o >>= 1) v += __shfl_xor_sync(0xffffffffu, v, o);

  __shared__ float red[8];
  __shared__ float sx[PHD];
  __shared__ float sinv;
  const int lane = d & 31, wp = d >> 5;
  if (lane == 0) red[wp] = v;
  __syncthreads();
  if (d == 0) {
    float s = 0.f;
#pragma unroll
    for (int i = 0; i < 8; i++) s += red[i];
    sinv = rsqrtf(s / (float)PHD + EPS_F);
  }
  __syncthreads();

  const float xn = x * sinv * (1.0f + w[d]);
  sx[d] = xn;
  __syncthreads();
  const float rot = (d < PHD / 2) ? -sx[d + PHD / 2] : sx[d - PHD / 2];
  const int s = m & (PS - 1);
  p[d] = xn * cost[(size_t)s * PHD + d] + rot * sint[(size_t)s * PHD + d];
}

// =====================================================================
// Sliding-window flash attention with tanh softcap (fp32).
// Reads Q/K/V from fused QKV buffer (row stride LDQKV).
// =====================================================================
#define TSTR 68
#define ATT_QT_OFF 0
#define ATT_KT_OFF (ATT_QT_OFF + 256 * TSTR)
#define ATT_VS_OFF (ATT_KT_OFF + 256 * TSTR)
#define ATT_PS_OFF (ATT_VS_OFF + 64 * 256)
#define ATT_RS_OFF (ATT_PS_OFF + 64 * 65)
#define ATT_LS_OFF (ATT_RS_OFF + 64)
#define ATT_SMEM_FLOATS (ATT_LS_OFF + 64)

__global__ void __launch_bounds__(256, 1) attn_kernel() {
  extern __shared__ float sm[];
  float* Qt = sm + ATT_QT_OFF;
  float* Kt = sm + ATT_KT_OFF;
  float* Vs = sm + ATT_VS_OFF;
  float* Ps = sm + ATT_PS_OFF;
  float* rs = sm + ATT_RS_OFF;
  float* ls = sm + ATT_LS_OFF;

  const int tid = threadIdx.x;
  const int t = blockIdx.x;
  const int h = blockIdx.y;
  const int b = blockIdx.z;
  const int i0 = t * 64;

  const float* Qg = g_QKV + (size_t)b * PS * LDQKV + h * PHD;
  const float* Kg = g_QKV + (size_t)b * PS * LDQKV + PQN;
  const float* Vg = g_QKV + (size_t)b * PS * LDQKV + PQN + PHD;
  float* Og = g_AO + ((size_t)b * PS * PNH + h) * PHD;

  for (int idx = tid; idx < 64 * 64; idx += 256) {
    const int q = idx >> 6;
    const int dv = (idx & 63) << 2;
    const float4 qv = *(const float4*)(Qg + (size_t)(i0 + q) * LDQKV + dv);
    Qt[(dv + 0) * TSTR + q] = qv.x * SCALE_F;
    Qt[(dv + 1) * TSTR + q] = qv.y * SCALE_F;
    Qt[(dv + 2) * TSTR + q] = qv.z * SCALE_F;
    Qt[(dv + 3) * TSTR + q] = qv.w * SCALE_F;
  }

  const int ty = tid >> 4, tx = tid & 15;
  const int qb = ty * 4, kb = tx * 4;

  float acc[4][16];
#pragma unroll
  for (int i = 0; i < 4; i++)
#pragma unroll
    for (int j = 0; j < 16; j++) acc[i][j] = 0.f;

  float mq = -1e30f, lq = 0.f;

  const int cstart = (t - 8 < 0) ? 0 : (t - 8);
  for (int c = cstart; c <= t; ++c) {
    const int j0 = c * 64;
    __syncthreads();
    for (int idx = tid; idx < 64 * 64; idx += 256) {
      const int k = idx >> 6;
      const int dv = (idx & 63) << 2;
      const float4 kv = *(const float4*)(Kg + (size_t)(j0 + k) * LDQKV + dv);
      Kt[(dv + 0) * TSTR + k] = kv.x;
      Kt[(dv + 1) * TSTR + k] = kv.y;
      Kt[(dv + 2) * TSTR + k] = kv.z;
      Kt[(dv + 3) * TSTR + k] = kv.w;
      *(float4*)(Vs + (size_t)k * PHD + dv) =
          *(const float4*)(Vg + (size_t)(j0 + k) * LDQKV + dv);
    }
    __syncthreads();

    float sc[4][4];
#pragma unroll
    for (int i = 0; i < 4; i++)
#pragma unroll
      for (int j = 0; j < 4; j++) sc[i][j] = 0.f;

    const float* qp = Qt + qb;
    const float* kp = Kt + kb;
#pragma unroll 4
    for (int dv = 0; dv < PHD; ++dv) {
      const float4 qv = *(const float4*)(qp + dv * TSTR);
      const float4 kv = *(const float4*)(kp + dv * TSTR);
      sc[0][0] += qv.x * kv.x; sc[0][1] += qv.x * kv.y; sc[0][2] += qv.x * kv.z; sc[0][3] += qv.x * kv.w;
      sc[1][0] += qv.y * kv.x; sc[1][1] += qv.y * kv.y; sc[1][2] += qv.y * kv.z; sc[1][3] += qv.y * kv.w;
      sc[2][0] += qv.z * kv.x; sc[2][1] += qv.z * kv.y; sc[2][2] += qv.z * kv.z; sc[2][3] += qv.z * kv.w;
      sc[3][0] += qv.w * kv.x; sc[3][1] += qv.w * kv.y; sc[3][2] += qv.w * kv.z; sc[3][3] += qv.w * kv.w;
    }

#pragma unroll
    for (int qi = 0; qi < 4; ++qi) {
      const int gi = i0 + qb + qi;
#pragma unroll
      for (int kj = 0; kj < 4; ++kj) {
        const int gj = j0 + kb + kj;
        const float capped = CAP_F * tanhf(sc[qi][kj] * (1.0f / CAP_F));
        const bool ok = (gj <= gi) && (gj > gi - WIN_I);
        Ps[(qb + qi) * 65 + (kb + kj)] = ok ? capped : -1e9f;
      }
    }
    __syncthreads();

    if (tid < 64) {
      float* pr = Ps + tid * 65;
      float mc = -1e30f;
#pragma unroll 8
      for (int k = 0; k < 64; ++k) mc = fmaxf(mc, pr[k]);
      const float mNew = fmaxf(mq, mc);
      const float r = __expf(mq - mNew);
      float sum = 0.f;
#pragma unroll 8
      for (int k = 0; k < 64; ++k) {
        const float sv = pr[k];
        const float p = (sv > -1e8f) ? __expf(sv - mNew) : 0.f;
        pr[k] = p;
        sum += p;
      }
      lq = lq * r + sum;
      mq = mNew;
      rs[tid] = r;
      ls[tid] = lq;
    }
    __syncthreads();

#pragma unroll
    for (int qi = 0; qi < 4; ++qi) {
      const float rr = rs[qb + qi];
#pragma unroll
      for (int j = 0; j < 16; ++j) acc[qi][j] *= rr;
    }
    const float* vp = Vs + tx * 4;
#pragma unroll 2
    for (int k = 0; k < 64; ++k) {
      float vv[16];
      *(float4*)(vv)      = *(const float4*)(vp + (size_t)k * PHD);
      *(float4*)(vv + 4)  = *(const float4*)(vp + (size_t)k * PHD + 64);
      *(float4*)(vv + 8)  = *(const float4*)(vp + (size_t)k * PHD + 128);
      *(float4*)(vv + 12) = *(const float4*)(vp + (size_t)k * PHD + 192);
#pragma unroll
      for (int qi = 0; qi < 4; ++qi) {
        const float p = Ps[(qb + qi) * 65 + k];
#pragma unroll
        for (int j = 0; j < 16; ++j) acc[qi][j] += p * vv[j];
      }
    }
  }

#pragma unroll
  for (int qi = 0; qi < 4; ++qi) {
    const float inv = 1.0f / ls[qb + qi];
    float* op = Og + (size_t)(i0 + qb + qi) * PQN;
#pragma unroll
    for (int g = 0; g < 4; ++g) {
      float4 o;
      o.x = acc[qi][g * 4 + 0] * inv;
      o.y = acc[qi][g * 4 + 1] * inv;
      o.z = acc[qi][g * 4 + 2] * inv;
      o.w = acc[qi][g * 4 + 3] * inv;
      *(float4*)(op + g * 64 + tx * 4) = o;
    }
  }
}

// =====================================================================
// launch
// =====================================================================
extern "C" void kernel_launch(void* const* d_in, const int* in_sizes, int n_in,
                              void* d_out, int out_size) {
  (void)in_sizes; (void)n_in; (void)out_size;
  const float* hidden = (const float*)d_in[0];
  const float* cost   = (const float*)d_in[1];
  const float* sint   = (const float*)d_in[2];
  // d_in[3] attention_mask: unused (mask computed analytically)
  const float* Wq = (const float*)d_in[4];
  const float* Wk = (const float*)d_in[5];
  const float* Wv = (const float*)d_in[6];
  const float* Wo = (const float*)d_in[7];
  const float* qw = (const float*)d_in[8];
  const float* kw = (const float*)d_in[9];
  float* out = (float*)d_out;

  float *QKVb, *AOb;
  cudaGetSymbolAddress((void**)&QKVb, g_QKV);
  cudaGetSymbolAddress((void**)&AOb, g_AO);
  unsigned short *Ahp, *Alp, *WBh, *WBl, *Woh, *Wol, *AOh, *AOl;
  cudaGetSymbolAddress((void**)&Ahp, g_Ah);
  cudaGetSymbolAddress((void**)&Alp, g_Al);
  cudaGetSymbolAddress((void**)&WBh, g_WBh);
  cudaGetSymbolAddress((void**)&WBl, g_WBl);
  cudaGetSymbolAddress((void**)&Woh, g_Woh);
  cudaGetSymbolAddress((void**)&Wol, g_Wol);
  cudaGetSymbolAddress((void**)&AOh, g_AOh);
  cudaGetSymbolAddress((void**)&AOl, g_AOl);

  cudaFuncSetAttribute(gemm_mma, cudaFuncAttributeMaxDynamicSharedMemorySize, GT_SMEM);

  // pre-split hidden + weights (combined QKV weight buffer, transposed)
  {
    const int n4 = PM * PHID / 4;
    split_elem<<<n4 / 256, 256>>>((const float4*)hidden, (ushort4*)Ahp, (ushort4*)Alp, n4);
  }
  transpose_split<<<dim3(PHID / 32, PQN / 32), 256>>>(Wq, WBh, WBl, PHID, PQN);
  transpose_split<<<dim3(PHID / 32, PHD / 32), 256>>>(
      Wk, WBh + (size_t)PQN * PHID, WBl + (size_t)PQN * PHID, PHID, PHD);
  transpose_split<<<dim3(PHID / 32, PHD / 32), 256>>>(
      Wv, WBh + (size_t)(PQN + PHD) * PHID, WBl + (size_t)(PQN + PHD) * PHID, PHID, PHD);
  transpose_split<<<dim3(PQN / 32, PHID / 32), 256>>>(Wo, Woh, Wol, PQN, PHID);

  // fused QKV projection
  gemm_mma<<<dim3(LDQKV / 128, PM / 128), 256, GT_SMEM>>>(
      Ahp, Alp, WBh, WBl, QKVb, PM, LDQKV, PHID);

  // RMSNorm + RoPE (Q heads, then K)
  normrope_kernel<<<dim3(PM, PNH), 256>>>(QKVb, LDQKV, qw, cost, sint);
  normrope_kernel<<<dim3(PM, 1), 256>>>(QKVb + PQN, LDQKV, kw, cost, sint);

  // attention
  const int smem_bytes = ATT_SMEM_FLOATS * (int)sizeof(float);
  cudaFuncSetAttribute(attn_kernel, cudaFuncAttributeMaxDynamicSharedMemorySize, smem_bytes);
  attn_kernel<<<dim3(PS / 64, PNH, PB), 256, smem_bytes>>>();

  // split AO, output projection
  {
    const int n4 = PM * PQN / 4;
    split_elem<<<n4 / 256, 256>>>((const float4*)AOb, (ushort4*)AOh, (ushort4*)AOl, n4);
  }
  gemm_mma<<<dim3(PHID / 128, PM / 128), 256, GT_SMEM>>>(
      AOh, AOl, Woh, Wol, out, PM, PHID, PQN);
}